// round 3
// baseline (speedup 1.0000x reference)
#include <cuda_runtime.h>
#include <cuda_bf16.h>

// Problem constants
#define N_NODES 50000
#define N_EDGES 800000
#define IN_F    128
#define OUT_F   64

// ---------------------------------------------------------------------------
// Device scratch (no allocations allowed)
// ---------------------------------------------------------------------------
__device__ int   g_row_cnt[N_NODES];          // histogram, then scatter cursor
__device__ int   g_row_ptr[N_NODES + 1];      // CSR row pointers
__device__ int2  g_edge_sorted[N_EDGES];      // packed (col, attr-bits)
__device__ float g_buf0[N_NODES * OUT_F];     // ping
__device__ float g_buf1[N_NODES * OUT_F];     // pong

// ---------------------------------------------------------------------------
// 1) zero histogram counters
// ---------------------------------------------------------------------------
__global__ void zero_cnt_kernel() {
    int i = blockIdx.x * blockDim.x + threadIdx.x;
    if (i < N_NODES) g_row_cnt[i] = 0;
}

// ---------------------------------------------------------------------------
// 2) histogram of destination rows; 4 edges/thread via int4
// ---------------------------------------------------------------------------
__global__ void hist_kernel(const int* __restrict__ ei) {
    int t = blockIdx.x * blockDim.x + threadIdx.x;
    int e = t * 4;
    if (e < N_EDGES) {
        int4 r = *(const int4*)&ei[e];
        atomicAdd(&g_row_cnt[r.x], 1);
        atomicAdd(&g_row_cnt[r.y], 1);
        atomicAdd(&g_row_cnt[r.z], 1);
        atomicAdd(&g_row_cnt[r.w], 1);
    }
}

// ---------------------------------------------------------------------------
// 3) exclusive scan over 50000 counters, single block of 1024 threads.
//    Writes g_row_ptr and re-initializes g_row_cnt as scatter cursor.
// ---------------------------------------------------------------------------
__global__ void scan_kernel() {
    __shared__ int sm[1024];
    const int CH = (N_NODES + 1023) / 1024;   // 49
    int t = threadIdx.x;
    int base = t * CH;

    int s = 0;
    for (int j = 0; j < CH; j++) {
        int i = base + j;
        if (i < N_NODES) s += g_row_cnt[i];
    }
    sm[t] = s;
    __syncthreads();

    // Hillis-Steele inclusive scan
    int v = s;
    for (int off = 1; off < 1024; off <<= 1) {
        int add = (t >= off) ? sm[t - off] : 0;
        __syncthreads();
        v += add;
        sm[t] = v;
        __syncthreads();
    }
    int run = v - s;  // exclusive prefix for this chunk

    for (int j = 0; j < CH; j++) {
        int i = base + j;
        if (i < N_NODES) {
            int c = g_row_cnt[i];
            g_row_ptr[i] = run;
            g_row_cnt[i] = run;   // cursor for scatter
            run += c;
        }
    }
    if (t == 0) g_row_ptr[N_NODES] = N_EDGES;
}

// ---------------------------------------------------------------------------
// 4) scatter edges into CSR order; 4 edges/thread, packed int2 payload
// ---------------------------------------------------------------------------
__global__ void scatter_kernel(const int* __restrict__ ei,
                               const float* __restrict__ attr) {
    int t = blockIdx.x * blockDim.x + threadIdx.x;
    int e = t * 4;
    if (e < N_EDGES) {
        int4   rows = *(const int4*)&ei[e];
        int4   cols = *(const int4*)&ei[N_EDGES + e];
        float4 at   = *(const float4*)&attr[e];

        int p0 = atomicAdd(&g_row_cnt[rows.x], 1);
        int p1 = atomicAdd(&g_row_cnt[rows.y], 1);
        int p2 = atomicAdd(&g_row_cnt[rows.z], 1);
        int p3 = atomicAdd(&g_row_cnt[rows.w], 1);
        g_edge_sorted[p0] = make_int2(cols.x, __float_as_int(at.x));
        g_edge_sorted[p1] = make_int2(cols.y, __float_as_int(at.y));
        g_edge_sorted[p2] = make_int2(cols.z, __float_as_int(at.z));
        g_edge_sorted[p3] = make_int2(cols.w, __float_as_int(at.w));
    }
}

// ---------------------------------------------------------------------------
// 5) GEMM: out[n,o] = sum_k x[n,k] * W[o,k] + b[o]
//    Block = 256 threads, tile 64 rows x 64 outs. W transposed in smem.
//    Thread computes 4 rows x 4 outs with float4 k-steps.
// ---------------------------------------------------------------------------
__global__ __launch_bounds__(256, 4)
void gemm_kernel(const float* __restrict__ x,
                 const float* __restrict__ W,
                 const float* __restrict__ b,
                 float* __restrict__ out) {
    __shared__ float Ws[IN_F * 68];   // transposed, padded row stride 68

    for (int idx = threadIdx.x; idx < OUT_F * IN_F; idx += 256) {
        int o = idx >> 7;       // 0..63
        int k = idx & 127;      // 0..127
        Ws[k * 68 + o] = W[idx];
    }
    __syncthreads();

    int rg = threadIdx.x >> 4;   // 0..15 -> 4 rows each
    int og = threadIdx.x & 15;   // 0..15 -> 4 outs each
    int row0 = blockIdx.x * 64 + rg * 4;

    float acc[4][4];
#pragma unroll
    for (int i = 0; i < 4; i++)
#pragma unroll
        for (int j = 0; j < 4; j++) acc[i][j] = 0.0f;

    int r[4];
#pragma unroll
    for (int i = 0; i < 4; i++) {
        int rr = row0 + i;
        r[i] = rr < N_NODES ? rr : N_NODES - 1;
    }

    for (int k = 0; k < IN_F; k += 4) {
        float4 wv[4];
#pragma unroll
        for (int kk = 0; kk < 4; kk++)
            wv[kk] = *(const float4*)&Ws[(k + kk) * 68 + og * 4];
#pragma unroll
        for (int i = 0; i < 4; i++) {
            float4 xv = __ldg((const float4*)&x[r[i] * IN_F + k]);
            acc[i][0] += xv.x * wv[0].x; acc[i][1] += xv.x * wv[0].y;
            acc[i][2] += xv.x * wv[0].z; acc[i][3] += xv.x * wv[0].w;
            acc[i][0] += xv.y * wv[1].x; acc[i][1] += xv.y * wv[1].y;
            acc[i][2] += xv.y * wv[1].z; acc[i][3] += xv.y * wv[1].w;
            acc[i][0] += xv.z * wv[2].x; acc[i][1] += xv.z * wv[2].y;
            acc[i][2] += xv.z * wv[2].z; acc[i][3] += xv.z * wv[2].w;
            acc[i][0] += xv.w * wv[3].x; acc[i][1] += xv.w * wv[3].y;
            acc[i][2] += xv.w * wv[3].z; acc[i][3] += xv.w * wv[3].w;
        }
    }

    float4 bias = __ldg((const float4*)&b[og * 4]);
#pragma unroll
    for (int i = 0; i < 4; i++) {
        int rr = row0 + i;
        if (rr < N_NODES) {
            float4 o4;
            o4.x = acc[i][0] + bias.x;
            o4.y = acc[i][1] + bias.y;
            o4.z = acc[i][2] + bias.z;
            o4.w = acc[i][3] + bias.w;
            *(float4*)&out[rr * OUT_F + og * 4] = o4;
        }
    }
}

// ---------------------------------------------------------------------------
// 6) SPMM (CSR, warp per row): out[r,:] = sum_e attr[e] * in[col[e],:]
//    Lane handles 2 features (float2). Unroll 4 with independent
//    accumulators so 4 gathers are in flight (MLP 4x).
// ---------------------------------------------------------------------------
__global__ __launch_bounds__(256, 8)
void spmm_kernel(const float* __restrict__ in, float* __restrict__ out) {
    int warp = (blockIdx.x * blockDim.x + threadIdx.x) >> 5;
    int lane = threadIdx.x & 31;
    if (warp >= N_NODES) return;

    int s = g_row_ptr[warp];
    int e = g_row_ptr[warp + 1];

    const float2* inp = (const float2*)in;
    float2 a0 = make_float2(0.f, 0.f);
    float2 a1 = make_float2(0.f, 0.f);
    float2 a2 = make_float2(0.f, 0.f);
    float2 a3 = make_float2(0.f, 0.f);

    int i = s;
    for (; i + 4 <= e; i += 4) {
        int2 e0 = __ldg(&g_edge_sorted[i]);
        int2 e1 = __ldg(&g_edge_sorted[i + 1]);
        int2 e2 = __ldg(&g_edge_sorted[i + 2]);
        int2 e3 = __ldg(&g_edge_sorted[i + 3]);
        float2 v0 = __ldg(&inp[e0.x * 32 + lane]);
        float2 v1 = __ldg(&inp[e1.x * 32 + lane]);
        float2 v2 = __ldg(&inp[e2.x * 32 + lane]);
        float2 v3 = __ldg(&inp[e3.x * 32 + lane]);
        float w0 = __int_as_float(e0.y);
        float w1 = __int_as_float(e1.y);
        float w2 = __int_as_float(e2.y);
        float w3 = __int_as_float(e3.y);
        a0.x += w0 * v0.x; a0.y += w0 * v0.y;
        a1.x += w1 * v1.x; a1.y += w1 * v1.y;
        a2.x += w2 * v2.x; a2.y += w2 * v2.y;
        a3.x += w3 * v3.x; a3.y += w3 * v3.y;
    }
    for (; i < e; i++) {
        int2 ed = __ldg(&g_edge_sorted[i]);
        float2 v = __ldg(&inp[ed.x * 32 + lane]);
        float w = __int_as_float(ed.y);
        a0.x += w * v.x; a0.y += w * v.y;
    }

    float2 acc;
    acc.x = (a0.x + a1.x) + (a2.x + a3.x);
    acc.y = (a0.y + a1.y) + (a2.y + a3.y);
    ((float2*)out)[warp * 32 + lane] = acc;
}

// ---------------------------------------------------------------------------
// launch
// ---------------------------------------------------------------------------
extern "C" void kernel_launch(void* const* d_in, const int* in_sizes, int n_in,
                              void* d_out, int out_size) {
    const float* x    = (const float*)d_in[0];
    const int*   ei   = (const int*)d_in[1];   // int32 (JAX x64 disabled)
    const float* attr = (const float*)d_in[2];
    const float* W    = (const float*)d_in[3];
    const float* b    = (const float*)d_in[4];
    float*       out  = (float*)d_out;

    // CSR build
    zero_cnt_kernel<<<(N_NODES + 255) / 256, 256>>>();
    hist_kernel<<<(N_EDGES / 4 + 255) / 256, 256>>>(ei);
    scan_kernel<<<1, 1024>>>();
    scatter_kernel<<<(N_EDGES / 4 + 255) / 256, 256>>>(ei, attr);

    // Resolve scratch pointers (host API, not a stream op — capture-legal).
    float *buf0, *buf1;
    cudaGetSymbolAddress((void**)&buf0, g_buf0);
    cudaGetSymbolAddress((void**)&buf1, g_buf1);

    // GEMM into buf0
    gemm_kernel<<<(N_NODES + 63) / 64, 256>>>(x, W, b, buf0);

    // 3 SPMM rounds: buf0 -> buf1 -> buf0 -> d_out
    int blocks = (N_NODES * 32 + 255) / 256;  // warp per row
    spmm_kernel<<<blocks, 256>>>(buf0, buf1);
    spmm_kernel<<<blocks, 256>>>(buf1, buf0);
    spmm_kernel<<<blocks, 256>>>(buf0, out);
}

// round 4
// speedup vs baseline: 1.0428x; 1.0428x over previous
#include <cuda_runtime.h>
#include <cuda_bf16.h>

// Problem constants
#define N_NODES 50000
#define N_EDGES 800000
#define IN_F    128
#define OUT_F   64

// ---------------------------------------------------------------------------
// Device scratch (no allocations allowed)
// ---------------------------------------------------------------------------
__device__ int   g_row_cnt[N_NODES];          // histogram, then scatter cursor
__device__ int   g_row_ptr[N_NODES + 1];      // CSR row pointers
__device__ int2  g_edge_sorted[N_EDGES];      // packed (col, attr-bits)
__device__ float g_buf0[N_NODES * OUT_F];     // ping
__device__ float g_buf1[N_NODES * OUT_F];     // pong

// ---------------------------------------------------------------------------
// histogram of destination rows; 4 edges/thread via int4
// ---------------------------------------------------------------------------
__global__ void hist_kernel(const int* __restrict__ ei) {
    int t = blockIdx.x * blockDim.x + threadIdx.x;
    int e = t * 4;
    if (e < N_EDGES) {
        int4 r = *(const int4*)&ei[e];
        atomicAdd(&g_row_cnt[r.x], 1);
        atomicAdd(&g_row_cnt[r.y], 1);
        atomicAdd(&g_row_cnt[r.z], 1);
        atomicAdd(&g_row_cnt[r.w], 1);
    }
}

// ---------------------------------------------------------------------------
// exclusive scan over 50000 counters, single block of 1024 threads.
// Writes g_row_ptr and re-initializes g_row_cnt as scatter cursor.
// ---------------------------------------------------------------------------
__global__ void scan_kernel() {
    __shared__ int sm[1024];
    const int CH = (N_NODES + 1023) / 1024;   // 49
    int t = threadIdx.x;
    int base = t * CH;

    int s = 0;
    for (int j = 0; j < CH; j++) {
        int i = base + j;
        if (i < N_NODES) s += g_row_cnt[i];
    }
    sm[t] = s;
    __syncthreads();

    int v = s;
    for (int off = 1; off < 1024; off <<= 1) {
        int add = (t >= off) ? sm[t - off] : 0;
        __syncthreads();
        v += add;
        sm[t] = v;
        __syncthreads();
    }
    int run = v - s;  // exclusive prefix for this chunk

    for (int j = 0; j < CH; j++) {
        int i = base + j;
        if (i < N_NODES) {
            int c = g_row_cnt[i];
            g_row_ptr[i] = run;
            g_row_cnt[i] = run;   // cursor for scatter
            run += c;
        }
    }
    if (t == 0) g_row_ptr[N_NODES] = N_EDGES;
}

// ---------------------------------------------------------------------------
// scatter edges into CSR order; 4 edges/thread, packed int2 payload
// ---------------------------------------------------------------------------
__global__ void scatter_kernel(const int* __restrict__ ei,
                               const float* __restrict__ attr) {
    int t = blockIdx.x * blockDim.x + threadIdx.x;
    int e = t * 4;
    if (e < N_EDGES) {
        int4   rows = *(const int4*)&ei[e];
        int4   cols = *(const int4*)&ei[N_EDGES + e];
        float4 at   = *(const float4*)&attr[e];

        int p0 = atomicAdd(&g_row_cnt[rows.x], 1);
        int p1 = atomicAdd(&g_row_cnt[rows.y], 1);
        int p2 = atomicAdd(&g_row_cnt[rows.z], 1);
        int p3 = atomicAdd(&g_row_cnt[rows.w], 1);
        g_edge_sorted[p0] = make_int2(cols.x, __float_as_int(at.x));
        g_edge_sorted[p1] = make_int2(cols.y, __float_as_int(at.y));
        g_edge_sorted[p2] = make_int2(cols.z, __float_as_int(at.z));
        g_edge_sorted[p3] = make_int2(cols.w, __float_as_int(at.w));
    }
}

// ---------------------------------------------------------------------------
// GEMM: out[n,o] = sum_k x[n,k] * W[o,k] + b[o]
// Block = 256 threads, tile 64 rows x 64 outs. W transposed in smem.
// ---------------------------------------------------------------------------
__global__ __launch_bounds__(256, 4)
void gemm_kernel(const float* __restrict__ x,
                 const float* __restrict__ W,
                 const float* __restrict__ b,
                 float* __restrict__ out) {
    __shared__ float Ws[IN_F * 68];

    for (int idx = threadIdx.x; idx < OUT_F * IN_F; idx += 256) {
        int o = idx >> 7;
        int k = idx & 127;
        Ws[k * 68 + o] = W[idx];
    }
    __syncthreads();

    int rg = threadIdx.x >> 4;
    int og = threadIdx.x & 15;
    int row0 = blockIdx.x * 64 + rg * 4;

    float acc[4][4];
#pragma unroll
    for (int i = 0; i < 4; i++)
#pragma unroll
        for (int j = 0; j < 4; j++) acc[i][j] = 0.0f;

    int r[4];
#pragma unroll
    for (int i = 0; i < 4; i++) {
        int rr = row0 + i;
        r[i] = rr < N_NODES ? rr : N_NODES - 1;
    }

    for (int k = 0; k < IN_F; k += 4) {
        float4 wv[4];
#pragma unroll
        for (int kk = 0; kk < 4; kk++)
            wv[kk] = *(const float4*)&Ws[(k + kk) * 68 + og * 4];
#pragma unroll
        for (int i = 0; i < 4; i++) {
            float4 xv = __ldg((const float4*)&x[r[i] * IN_F + k]);
            acc[i][0] += xv.x * wv[0].x; acc[i][1] += xv.x * wv[0].y;
            acc[i][2] += xv.x * wv[0].z; acc[i][3] += xv.x * wv[0].w;
            acc[i][0] += xv.y * wv[1].x; acc[i][1] += xv.y * wv[1].y;
            acc[i][2] += xv.y * wv[1].z; acc[i][3] += xv.y * wv[1].w;
            acc[i][0] += xv.z * wv[2].x; acc[i][1] += xv.z * wv[2].y;
            acc[i][2] += xv.z * wv[2].z; acc[i][3] += xv.z * wv[2].w;
            acc[i][0] += xv.w * wv[3].x; acc[i][1] += xv.w * wv[3].y;
            acc[i][2] += xv.w * wv[3].z; acc[i][3] += xv.w * wv[3].w;
        }
    }

    float4 bias = __ldg((const float4*)&b[og * 4]);
#pragma unroll
    for (int i = 0; i < 4; i++) {
        int rr = row0 + i;
        if (rr < N_NODES) {
            float4 o4;
            o4.x = acc[i][0] + bias.x;
            o4.y = acc[i][1] + bias.y;
            o4.z = acc[i][2] + bias.z;
            o4.w = acc[i][3] + bias.w;
            *(float4*)&out[rr * OUT_F + og * 4] = o4;
        }
    }
}

// ---------------------------------------------------------------------------
// SPMM (CSR): 2 rows per warp, 16 lanes per row, float4 per lane.
// out[r,:] = sum_e attr[e] * in[col[e],:]
// Halved LDG count vs 1-row/warp float2 while keeping identical traffic;
// two independent edge loops per warp give extra latency overlap.
// ---------------------------------------------------------------------------
__global__ __launch_bounds__(256, 8)
void spmm_kernel(const float* __restrict__ in, float* __restrict__ out) {
    int warp = (blockIdx.x * blockDim.x + threadIdx.x) >> 5;
    int lane = threadIdx.x & 31;
    int half = lane >> 4;      // 0 or 1: which row this half-warp handles
    int fl   = lane & 15;      // feature lane: 4 floats each (64 = 16*4)

    int row = warp * 2 + half;
    if (row >= N_NODES) return;

    int s = g_row_ptr[row];
    int e = g_row_ptr[row + 1];

    const float4* inp = (const float4*)in;
    float4 a0 = make_float4(0.f, 0.f, 0.f, 0.f);
    float4 a1 = make_float4(0.f, 0.f, 0.f, 0.f);
    float4 a2 = make_float4(0.f, 0.f, 0.f, 0.f);
    float4 a3 = make_float4(0.f, 0.f, 0.f, 0.f);

    int i = s;
    for (; i + 4 <= e; i += 4) {
        int2 e0 = __ldg(&g_edge_sorted[i]);
        int2 e1 = __ldg(&g_edge_sorted[i + 1]);
        int2 e2 = __ldg(&g_edge_sorted[i + 2]);
        int2 e3 = __ldg(&g_edge_sorted[i + 3]);
        float4 v0 = __ldg(&inp[e0.x * 16 + fl]);
        float4 v1 = __ldg(&inp[e1.x * 16 + fl]);
        float4 v2 = __ldg(&inp[e2.x * 16 + fl]);
        float4 v3 = __ldg(&inp[e3.x * 16 + fl]);
        float w0 = __int_as_float(e0.y);
        float w1 = __int_as_float(e1.y);
        float w2 = __int_as_float(e2.y);
        float w3 = __int_as_float(e3.y);
        a0.x += w0 * v0.x; a0.y += w0 * v0.y; a0.z += w0 * v0.z; a0.w += w0 * v0.w;
        a1.x += w1 * v1.x; a1.y += w1 * v1.y; a1.z += w1 * v1.z; a1.w += w1 * v1.w;
        a2.x += w2 * v2.x; a2.y += w2 * v2.y; a2.z += w2 * v2.z; a2.w += w2 * v2.w;
        a3.x += w3 * v3.x; a3.y += w3 * v3.y; a3.z += w3 * v3.z; a3.w += w3 * v3.w;
    }
    for (; i < e; i++) {
        int2 ed = __ldg(&g_edge_sorted[i]);
        float4 v = __ldg(&inp[ed.x * 16 + fl]);
        float w = __int_as_float(ed.y);
        a0.x += w * v.x; a0.y += w * v.y; a0.z += w * v.z; a0.w += w * v.w;
    }

    float4 acc;
    acc.x = (a0.x + a1.x) + (a2.x + a3.x);
    acc.y = (a0.y + a1.y) + (a2.y + a3.y);
    acc.z = (a0.z + a1.z) + (a2.z + a3.z);
    acc.w = (a0.w + a1.w) + (a2.w + a3.w);
    ((float4*)out)[row * 16 + fl] = acc;
}

// ---------------------------------------------------------------------------
// launch: fork GEMM onto a side stream, overlapping with CSR build
// ---------------------------------------------------------------------------
extern "C" void kernel_launch(void* const* d_in, const int* in_sizes, int n_in,
                              void* d_out, int out_size) {
    const float* x    = (const float*)d_in[0];
    const int*   ei   = (const int*)d_in[1];   // int32 (JAX x64 disabled)
    const float* attr = (const float*)d_in[2];
    const float* W    = (const float*)d_in[3];
    const float* b    = (const float*)d_in[4];
    float*       out  = (float*)d_out;

    // Scratch pointers (host API, not a stream op — capture-legal).
    float *buf0, *buf1;
    int   *cnt;
    cudaGetSymbolAddress((void**)&buf0, g_buf0);
    cudaGetSymbolAddress((void**)&buf1, g_buf1);
    cudaGetSymbolAddress((void**)&cnt,  g_row_cnt);

    // Fork a side stream into the capture for the (independent) GEMM.
    cudaStream_t s2;
    cudaStreamCreateWithFlags(&s2, cudaStreamNonBlocking);
    cudaEvent_t ev_fork, ev_join;
    cudaEventCreateWithFlags(&ev_fork, cudaEventDisableTiming);
    cudaEventCreateWithFlags(&ev_join, cudaEventDisableTiming);

    cudaEventRecord(ev_fork, 0);
    cudaStreamWaitEvent(s2, ev_fork, 0);

    // Side stream: GEMM into buf0 (independent of CSR build)
    gemm_kernel<<<(N_NODES + 63) / 64, 256, 0, s2>>>(x, W, b, buf0);
    cudaEventRecord(ev_join, s2);

    // Main stream: CSR build
    cudaMemsetAsync(cnt, 0, N_NODES * sizeof(int), 0);
    hist_kernel<<<(N_EDGES / 4 + 255) / 256, 256>>>(ei);
    scan_kernel<<<1, 1024>>>();
    scatter_kernel<<<(N_EDGES / 4 + 255) / 256, 256>>>(ei, attr);

    // Join GEMM before first SPMM
    cudaStreamWaitEvent(0, ev_join, 0);

    // 3 SPMM rounds: buf0 -> buf1 -> buf0 -> d_out  (2 rows per warp)
    int blocks = (N_NODES / 2 * 32 + 255) / 256;
    spmm_kernel<<<blocks, 256>>>(buf0, buf1);
    spmm_kernel<<<blocks, 256>>>(buf1, buf0);
    spmm_kernel<<<blocks, 256>>>(buf0, out);
}

// round 5
// speedup vs baseline: 1.0673x; 1.0235x over previous
#include <cuda_runtime.h>
#include <cuda_fp16.h>

// Problem constants
#define N_NODES 50000
#define N_EDGES 800000
#define IN_F    128
#define OUT_F   64

// ---------------------------------------------------------------------------
// Device scratch (no allocations allowed)
// ---------------------------------------------------------------------------
__device__ int    g_row_cnt[N_NODES];          // histogram, then scatter cursor
__device__ int    g_row_ptr[N_NODES + 1];      // CSR row pointers
__device__ int2   g_edge_sorted[N_EDGES];      // packed (col, attr-bits fp32)
__device__ __half g_h0[N_NODES * OUT_F];       // ping (fp16 features)
__device__ __half g_h1[N_NODES * OUT_F];       // pong (fp16 features)

// ---------------------------------------------------------------------------
// histogram of destination rows; 1 edge/thread (max TLP to hide atomic lat)
// ---------------------------------------------------------------------------
__global__ void hist_kernel(const int* __restrict__ ei) {
    int e = blockIdx.x * blockDim.x + threadIdx.x;
    if (e < N_EDGES) atomicAdd(&g_row_cnt[ei[e]], 1);
}

// ---------------------------------------------------------------------------
// exclusive scan over 50000 counters, single block of 1024 threads.
// ---------------------------------------------------------------------------
__global__ void scan_kernel() {
    __shared__ int sm[1024];
    const int CH = (N_NODES + 1023) / 1024;   // 49
    int t = threadIdx.x;
    int base = t * CH;

    int s = 0;
    for (int j = 0; j < CH; j++) {
        int i = base + j;
        if (i < N_NODES) s += g_row_cnt[i];
    }
    sm[t] = s;
    __syncthreads();

    int v = s;
    for (int off = 1; off < 1024; off <<= 1) {
        int add = (t >= off) ? sm[t - off] : 0;
        __syncthreads();
        v += add;
        sm[t] = v;
        __syncthreads();
    }
    int run = v - s;

    for (int j = 0; j < CH; j++) {
        int i = base + j;
        if (i < N_NODES) {
            int c = g_row_cnt[i];
            g_row_ptr[i] = run;
            g_row_cnt[i] = run;   // cursor for scatter
            run += c;
        }
    }
    if (t == 0) g_row_ptr[N_NODES] = N_EDGES;
}

// ---------------------------------------------------------------------------
// scatter edges into CSR order; 1 edge/thread
// ---------------------------------------------------------------------------
__global__ void scatter_kernel(const int* __restrict__ ei,
                               const float* __restrict__ attr) {
    int e = blockIdx.x * blockDim.x + threadIdx.x;
    if (e < N_EDGES) {
        int row = ei[e];
        int col = ei[N_EDGES + e];
        float a = attr[e];
        int pos = atomicAdd(&g_row_cnt[row], 1);
        g_edge_sorted[pos] = make_int2(col, __float_as_int(a));
    }
}

// ---------------------------------------------------------------------------
// GEMM: out[n,o] = sum_k x[n,k] * W[o,k] + b[o]   (fp32 math, fp16 store)
// ---------------------------------------------------------------------------
__global__ __launch_bounds__(256, 4)
void gemm_kernel(const float* __restrict__ x,
                 const float* __restrict__ W,
                 const float* __restrict__ b,
                 __half* __restrict__ out) {
    __shared__ float Ws[IN_F * 68];

    for (int idx = threadIdx.x; idx < OUT_F * IN_F; idx += 256) {
        int o = idx >> 7;
        int k = idx & 127;
        Ws[k * 68 + o] = W[idx];
    }
    __syncthreads();

    int rg = threadIdx.x >> 4;
    int og = threadIdx.x & 15;
    int row0 = blockIdx.x * 64 + rg * 4;

    float acc[4][4];
#pragma unroll
    for (int i = 0; i < 4; i++)
#pragma unroll
        for (int j = 0; j < 4; j++) acc[i][j] = 0.0f;

    int r[4];
#pragma unroll
    for (int i = 0; i < 4; i++) {
        int rr = row0 + i;
        r[i] = rr < N_NODES ? rr : N_NODES - 1;
    }

    for (int k = 0; k < IN_F; k += 4) {
        float4 wv[4];
#pragma unroll
        for (int kk = 0; kk < 4; kk++)
            wv[kk] = *(const float4*)&Ws[(k + kk) * 68 + og * 4];
#pragma unroll
        for (int i = 0; i < 4; i++) {
            float4 xv = __ldg((const float4*)&x[r[i] * IN_F + k]);
            acc[i][0] += xv.x * wv[0].x; acc[i][1] += xv.x * wv[0].y;
            acc[i][2] += xv.x * wv[0].z; acc[i][3] += xv.x * wv[0].w;
            acc[i][0] += xv.y * wv[1].x; acc[i][1] += xv.y * wv[1].y;
            acc[i][2] += xv.y * wv[1].z; acc[i][3] += xv.y * wv[1].w;
            acc[i][0] += xv.z * wv[2].x; acc[i][1] += xv.z * wv[2].y;
            acc[i][2] += xv.z * wv[2].z; acc[i][3] += xv.z * wv[2].w;
            acc[i][0] += xv.w * wv[3].x; acc[i][1] += xv.w * wv[3].y;
            acc[i][2] += xv.w * wv[3].z; acc[i][3] += xv.w * wv[3].w;
        }
    }

    float4 bias = __ldg((const float4*)&b[og * 4]);
#pragma unroll
    for (int i = 0; i < 4; i++) {
        int rr = row0 + i;
        if (rr < N_NODES) {
            __half2 h0 = __floats2half2_rn(acc[i][0] + bias.x, acc[i][1] + bias.y);
            __half2 h1 = __floats2half2_rn(acc[i][2] + bias.z, acc[i][3] + bias.w);
            uint2 st;
            st.x = *(unsigned int*)&h0;
            st.y = *(unsigned int*)&h1;
            ((uint2*)out)[rr * 16 + og] = st;
        }
    }
}

// ---------------------------------------------------------------------------
// SPMM (CSR): 2 rows/warp, 16 lanes/row, 4 fp16 feats per lane (8B gather).
// fp32 accumulate. FINAL=true writes fp32 to d_out, else fp16.
// Gather per edge = 128 B = 1 L2 line.
// ---------------------------------------------------------------------------
template <bool FINAL>
__global__ __launch_bounds__(256, 8)
void spmm_kernel(const __half* __restrict__ in, void* __restrict__ outv) {
    int warp = (blockIdx.x * blockDim.x + threadIdx.x) >> 5;
    int lane = threadIdx.x & 31;
    int half_id = lane >> 4;
    int fl      = lane & 15;

    int row = warp * 2 + half_id;
    if (row >= N_NODES) return;

    int s = __ldg(&g_row_ptr[row]);
    int e = __ldg(&g_row_ptr[row + 1]);

    const uint2* inp = (const uint2*)in;   // 8B = 4 halves per lane
    float4 a0 = make_float4(0.f, 0.f, 0.f, 0.f);
    float4 a1 = make_float4(0.f, 0.f, 0.f, 0.f);
    float4 a2 = make_float4(0.f, 0.f, 0.f, 0.f);
    float4 a3 = make_float4(0.f, 0.f, 0.f, 0.f);

    int i = s;
    for (; i + 4 <= e; i += 4) {
        int2 e0 = __ldg(&g_edge_sorted[i]);
        int2 e1 = __ldg(&g_edge_sorted[i + 1]);
        int2 e2 = __ldg(&g_edge_sorted[i + 2]);
        int2 e3 = __ldg(&g_edge_sorted[i + 3]);
        uint2 v0 = __ldg(&inp[e0.x * 16 + fl]);
        uint2 v1 = __ldg(&inp[e1.x * 16 + fl]);
        uint2 v2 = __ldg(&inp[e2.x * 16 + fl]);
        uint2 v3 = __ldg(&inp[e3.x * 16 + fl]);
        float w0 = __int_as_float(e0.y);
        float w1 = __int_as_float(e1.y);
        float w2 = __int_as_float(e2.y);
        float w3 = __int_as_float(e3.y);

        float2 f;
        f = __half22float2(*(__half2*)&v0.x); a0.x += w0 * f.x; a0.y += w0 * f.y;
        f = __half22float2(*(__half2*)&v0.y); a0.z += w0 * f.x; a0.w += w0 * f.y;
        f = __half22float2(*(__half2*)&v1.x); a1.x += w1 * f.x; a1.y += w1 * f.y;
        f = __half22float2(*(__half2*)&v1.y); a1.z += w1 * f.x; a1.w += w1 * f.y;
        f = __half22float2(*(__half2*)&v2.x); a2.x += w2 * f.x; a2.y += w2 * f.y;
        f = __half22float2(*(__half2*)&v2.y); a2.z += w2 * f.x; a2.w += w2 * f.y;
        f = __half22float2(*(__half2*)&v3.x); a3.x += w3 * f.x; a3.y += w3 * f.y;
        f = __half22float2(*(__half2*)&v3.y); a3.z += w3 * f.x; a3.w += w3 * f.y;
    }
    for (; i < e; i++) {
        int2 ed = __ldg(&g_edge_sorted[i]);
        uint2 v = __ldg(&inp[ed.x * 16 + fl]);
        float w = __int_as_float(ed.y);
        float2 f;
        f = __half22float2(*(__half2*)&v.x); a0.x += w * f.x; a0.y += w * f.y;
        f = __half22float2(*(__half2*)&v.y); a0.z += w * f.x; a0.w += w * f.y;
    }

    float4 acc;
    acc.x = (a0.x + a1.x) + (a2.x + a3.x);
    acc.y = (a0.y + a1.y) + (a2.y + a3.y);
    acc.z = (a0.z + a1.z) + (a2.z + a3.z);
    acc.w = (a0.w + a1.w) + (a2.w + a3.w);

    if (FINAL) {
        ((float4*)outv)[row * 16 + fl] = acc;
    } else {
        __half2 h0 = __floats2half2_rn(acc.x, acc.y);
        __half2 h1 = __floats2half2_rn(acc.z, acc.w);
        uint2 st;
        st.x = *(unsigned int*)&h0;
        st.y = *(unsigned int*)&h1;
        ((uint2*)outv)[row * 16 + fl] = st;
    }
}

// ---------------------------------------------------------------------------
// launch: fork GEMM onto a side stream, overlapping with CSR build
// ---------------------------------------------------------------------------
extern "C" void kernel_launch(void* const* d_in, const int* in_sizes, int n_in,
                              void* d_out, int out_size) {
    const float* x    = (const float*)d_in[0];
    const int*   ei   = (const int*)d_in[1];   // int32 (JAX x64 disabled)
    const float* attr = (const float*)d_in[2];
    const float* W    = (const float*)d_in[3];
    const float* b    = (const float*)d_in[4];
    float*       out  = (float*)d_out;

    __half *h0, *h1;
    int    *cnt;
    cudaGetSymbolAddress((void**)&h0,  g_h0);
    cudaGetSymbolAddress((void**)&h1,  g_h1);
    cudaGetSymbolAddress((void**)&cnt, g_row_cnt);

    // Fork side stream for the independent GEMM.
    cudaStream_t s2;
    cudaStreamCreateWithFlags(&s2, cudaStreamNonBlocking);
    cudaEvent_t ev_fork, ev_join;
    cudaEventCreateWithFlags(&ev_fork, cudaEventDisableTiming);
    cudaEventCreateWithFlags(&ev_join, cudaEventDisableTiming);

    cudaEventRecord(ev_fork, 0);
    cudaStreamWaitEvent(s2, ev_fork, 0);

    gemm_kernel<<<(N_NODES + 63) / 64, 256, 0, s2>>>(x, W, b, h0);
    cudaEventRecord(ev_join, s2);

    // Main stream: CSR build
    cudaMemsetAsync(cnt, 0, N_NODES * sizeof(int), 0);
    hist_kernel<<<(N_EDGES + 255) / 256, 256>>>(ei);
    scan_kernel<<<1, 1024>>>();
    scatter_kernel<<<(N_EDGES + 255) / 256, 256>>>(ei, attr);

    cudaStreamWaitEvent(0, ev_join, 0);

    // 3 SPMM rounds: h0 -> h1 -> h0 -> d_out (fp32)
    int blocks = (N_NODES / 2 * 32 + 255) / 256;
    spmm_kernel<false><<<blocks, 256>>>(h0, h1);
    spmm_kernel<false><<<blocks, 256>>>(h1, h0);
    spmm_kernel<true ><<<blocks, 256>>>(h0, out);
}

// round 6
// speedup vs baseline: 1.0794x; 1.0114x over previous
#include <cuda_runtime.h>
#include <cuda_fp16.h>
#include <mma.h>

using namespace nvcuda;

// Problem constants
#define N_NODES 50000
#define N_EDGES 800000
#define IN_F    128
#define OUT_F   64

// ---------------------------------------------------------------------------
// Device scratch (no allocations allowed)
// ---------------------------------------------------------------------------
__device__ int    g_row_cnt[N_NODES];          // histogram, then scatter cursor
__device__ int    g_row_ptr[N_NODES + 1];      // CSR row pointers
__device__ int2   g_edge_sorted[N_EDGES];      // packed (col, attr-bits fp32)
__device__ __half g_h0[N_NODES * OUT_F];       // ping (fp16 features)
__device__ __half g_h1[N_NODES * OUT_F];       // pong (fp16 features)

// ---------------------------------------------------------------------------
// histogram of destination rows; 1 edge/thread
// ---------------------------------------------------------------------------
__global__ void hist_kernel(const int* __restrict__ ei) {
    int e = blockIdx.x * blockDim.x + threadIdx.x;
    if (e < N_EDGES) atomicAdd(&g_row_cnt[ei[e]], 1);
}

// ---------------------------------------------------------------------------
// exclusive scan over 50000 counters, single block of 1024 threads.
// ---------------------------------------------------------------------------
__global__ void scan_kernel() {
    __shared__ int sm[1024];
    const int CH = (N_NODES + 1023) / 1024;   // 49
    int t = threadIdx.x;
    int base = t * CH;

    int s = 0;
    for (int j = 0; j < CH; j++) {
        int i = base + j;
        if (i < N_NODES) s += g_row_cnt[i];
    }
    sm[t] = s;
    __syncthreads();

    int v = s;
    for (int off = 1; off < 1024; off <<= 1) {
        int add = (t >= off) ? sm[t - off] : 0;
        __syncthreads();
        v += add;
        sm[t] = v;
        __syncthreads();
    }
    int run = v - s;

    for (int j = 0; j < CH; j++) {
        int i = base + j;
        if (i < N_NODES) {
            int c = g_row_cnt[i];
            g_row_ptr[i] = run;
            g_row_cnt[i] = run;   // cursor for scatter
            run += c;
        }
    }
    if (t == 0) g_row_ptr[N_NODES] = N_EDGES;
}

// ---------------------------------------------------------------------------
// scatter edges into CSR order; 1 edge/thread
// ---------------------------------------------------------------------------
__global__ void scatter_kernel(const int* __restrict__ ei,
                               const float* __restrict__ attr) {
    int e = blockIdx.x * blockDim.x + threadIdx.x;
    if (e < N_EDGES) {
        int row = ei[e];
        int col = ei[N_EDGES + e];
        float a = attr[e];
        int pos = atomicAdd(&g_row_cnt[row], 1);
        g_edge_sorted[pos] = make_int2(col, __float_as_int(a));
    }
}

// ---------------------------------------------------------------------------
// GEMM via tensor cores: out[n,o] = sum_k x[n,k] * W[o,k] + b[o]
// fp16 inputs (converted on the fly), fp32 accumulate, fp16 store.
// Block = 128 threads (4 warps), tile 64 rows x 64 outs, K = 128.
// Warp w computes rows [w*16, w*16+16) x all 64 outs (4 wmma col tiles).
// ---------------------------------------------------------------------------
__global__ __launch_bounds__(128)
void gemm_wmma_kernel(const float* __restrict__ x,
                      const float* __restrict__ W,
                      const float* __restrict__ b,
                      __half* __restrict__ out) {
    __shared__ __half Xs[64 * 128];    // x tile, row-major, ld 128 (16 KB)
    __shared__ __half Wsh[64 * 128];   // W fp16 copy [o][k], ld 128 (16 KB)

    int tid  = threadIdx.x;
    int warp = tid >> 5;
    int lane = tid & 31;
    int row0 = blockIdx.x * 64;

    // Convert W (64x128 fp32) -> fp16 smem. 2048 float4 / 128 threads.
    for (int i = tid; i < 64 * 128 / 4; i += 128) {
        float4 v = __ldg((const float4*)W + i);
        __half2 h0 = __floats2half2_rn(v.x, v.y);
        __half2 h1 = __floats2half2_rn(v.z, v.w);
        ((__half2*)Wsh)[i * 2]     = h0;
        ((__half2*)Wsh)[i * 2 + 1] = h1;
    }
    // Convert x tile (64x128 fp32) -> fp16 smem (rows clamped for OOB).
    for (int i = tid; i < 64 * 128 / 4; i += 128) {
        int r = i >> 5;       // 32 float4 per row
        int c = i & 31;
        int gr = row0 + r;
        if (gr >= N_NODES) gr = N_NODES - 1;
        float4 v = __ldg((const float4*)&x[gr * IN_F] + c);
        __half2 h0 = __floats2half2_rn(v.x, v.y);
        __half2 h1 = __floats2half2_rn(v.z, v.w);
        ((__half2*)Xs)[i * 2]     = h0;
        ((__half2*)Xs)[i * 2 + 1] = h1;
    }
    __syncthreads();

    wmma::fragment<wmma::accumulator, 16, 16, 16, float> acc[4];
#pragma unroll
    for (int j = 0; j < 4; j++) wmma::fill_fragment(acc[j], 0.0f);

#pragma unroll
    for (int k = 0; k < IN_F; k += 16) {
        wmma::fragment<wmma::matrix_a, 16, 16, 16, __half, wmma::row_major> af;
        wmma::load_matrix_sync(af, Xs + (warp * 16) * 128 + k, 128);
#pragma unroll
        for (int j = 0; j < 4; j++) {
            // B(kk, n) = W[n][kk] -> col_major with ld 128
            wmma::fragment<wmma::matrix_b, 16, 16, 16, __half, wmma::col_major> bf;
            wmma::load_matrix_sync(bf, Wsh + (j * 16) * 128 + k, 128);
            wmma::mma_sync(acc[j], af, bf, acc[j]);
        }
    }

    // Stage accumulators in smem (reuse Xs: 16 KB = 64x64 fp32).
    __syncthreads();   // all warps done reading Xs
    float* stage = (float*)Xs;                 // [64][64], ld 64
    float* st = stage + warp * 16 * 64;        // this warp's 16 rows
#pragma unroll
    for (int j = 0; j < 4; j++)
        wmma::store_matrix_sync(st + j * 16, acc[j], 64, wmma::mem_row_major);
    __syncwarp();

    // Bias + fp16 store. 16 rows x 16 uint2 (4 halves) = 256 items / 32 lanes.
    for (int it = lane; it < 16 * 16; it += 32) {
        int r  = it >> 4;
        int c4 = it & 15;
        int gr = row0 + warp * 16 + r;
        if (gr < N_NODES) {
            float4 bias = __ldg((const float4*)b + c4);
            float v0 = st[r * 64 + c4 * 4 + 0] + bias.x;
            float v1 = st[r * 64 + c4 * 4 + 1] + bias.y;
            float v2 = st[r * 64 + c4 * 4 + 2] + bias.z;
            float v3 = st[r * 64 + c4 * 4 + 3] + bias.w;
            __half2 h0 = __floats2half2_rn(v0, v1);
            __half2 h1 = __floats2half2_rn(v2, v3);
            uint2 u;
            u.x = *(unsigned int*)&h0;
            u.y = *(unsigned int*)&h1;
            ((uint2*)out)[gr * 16 + c4] = u;
        }
    }
}

// ---------------------------------------------------------------------------
// SPMM (CSR): 2 rows/warp, 16 lanes/row, 4 fp16 feats per lane (8B gather).
// fp32 accumulate. FINAL=true writes fp32 to d_out, else fp16.
// ---------------------------------------------------------------------------
template <bool FINAL>
__global__ __launch_bounds__(256, 8)
void spmm_kernel(const __half* __restrict__ in, void* __restrict__ outv) {
    int warp = (blockIdx.x * blockDim.x + threadIdx.x) >> 5;
    int lane = threadIdx.x & 31;
    int half_id = lane >> 4;
    int fl      = lane & 15;

    int row = warp * 2 + half_id;
    if (row >= N_NODES) return;

    int s = __ldg(&g_row_ptr[row]);
    int e = __ldg(&g_row_ptr[row + 1]);

    const uint2* inp = (const uint2*)in;
    float4 a0 = make_float4(0.f, 0.f, 0.f, 0.f);
    float4 a1 = make_float4(0.f, 0.f, 0.f, 0.f);
    float4 a2 = make_float4(0.f, 0.f, 0.f, 0.f);
    float4 a3 = make_float4(0.f, 0.f, 0.f, 0.f);

    int i = s;
    for (; i + 4 <= e; i += 4) {
        int2 e0 = __ldg(&g_edge_sorted[i]);
        int2 e1 = __ldg(&g_edge_sorted[i + 1]);
        int2 e2 = __ldg(&g_edge_sorted[i + 2]);
        int2 e3 = __ldg(&g_edge_sorted[i + 3]);
        uint2 v0 = __ldg(&inp[e0.x * 16 + fl]);
        uint2 v1 = __ldg(&inp[e1.x * 16 + fl]);
        uint2 v2 = __ldg(&inp[e2.x * 16 + fl]);
        uint2 v3 = __ldg(&inp[e3.x * 16 + fl]);
        float w0 = __int_as_float(e0.y);
        float w1 = __int_as_float(e1.y);
        float w2 = __int_as_float(e2.y);
        float w3 = __int_as_float(e3.y);

        float2 f;
        f = __half22float2(*(__half2*)&v0.x); a0.x += w0 * f.x; a0.y += w0 * f.y;
        f = __half22float2(*(__half2*)&v0.y); a0.z += w0 * f.x; a0.w += w0 * f.y;
        f = __half22float2(*(__half2*)&v1.x); a1.x += w1 * f.x; a1.y += w1 * f.y;
        f = __half22float2(*(__half2*)&v1.y); a1.z += w1 * f.x; a1.w += w1 * f.y;
        f = __half22float2(*(__half2*)&v2.x); a2.x += w2 * f.x; a2.y += w2 * f.y;
        f = __half22float2(*(__half2*)&v2.y); a2.z += w2 * f.x; a2.w += w2 * f.y;
        f = __half22float2(*(__half2*)&v3.x); a3.x += w3 * f.x; a3.y += w3 * f.y;
        f = __half22float2(*(__half2*)&v3.y); a3.z += w3 * f.x; a3.w += w3 * f.y;
    }
    for (; i < e; i++) {
        int2 ed = __ldg(&g_edge_sorted[i]);
        uint2 v = __ldg(&inp[ed.x * 16 + fl]);
        float w = __int_as_float(ed.y);
        float2 f;
        f = __half22float2(*(__half2*)&v.x); a0.x += w * f.x; a0.y += w * f.y;
        f = __half22float2(*(__half2*)&v.y); a0.z += w * f.x; a0.w += w * f.y;
    }

    float4 acc;
    acc.x = (a0.x + a1.x) + (a2.x + a3.x);
    acc.y = (a0.y + a1.y) + (a2.y + a3.y);
    acc.z = (a0.z + a1.z) + (a2.z + a3.z);
    acc.w = (a0.w + a1.w) + (a2.w + a3.w);

    if (FINAL) {
        ((float4*)outv)[row * 16 + fl] = acc;
    } else {
        __half2 h0 = __floats2half2_rn(acc.x, acc.y);
        __half2 h1 = __floats2half2_rn(acc.z, acc.w);
        uint2 st;
        st.x = *(unsigned int*)&h0;
        st.y = *(unsigned int*)&h1;
        ((uint2*)outv)[row * 16 + fl] = st;
    }
}

// ---------------------------------------------------------------------------
// launch: fork GEMM onto a side stream, overlapping with CSR build
// ---------------------------------------------------------------------------
extern "C" void kernel_launch(void* const* d_in, const int* in_sizes, int n_in,
                              void* d_out, int out_size) {
    const float* x    = (const float*)d_in[0];
    const int*   ei   = (const int*)d_in[1];   // int32 (JAX x64 disabled)
    const float* attr = (const float*)d_in[2];
    const float* W    = (const float*)d_in[3];
    const float* b    = (const float*)d_in[4];
    float*       out  = (float*)d_out;

    __half *h0, *h1;
    int    *cnt;
    cudaGetSymbolAddress((void**)&h0,  g_h0);
    cudaGetSymbolAddress((void**)&h1,  g_h1);
    cudaGetSymbolAddress((void**)&cnt, g_row_cnt);

    // Fork side stream for the independent GEMM.
    cudaStream_t s2;
    cudaStreamCreateWithFlags(&s2, cudaStreamNonBlocking);
    cudaEvent_t ev_fork, ev_join;
    cudaEventCreateWithFlags(&ev_fork, cudaEventDisableTiming);
    cudaEventCreateWithFlags(&ev_join, cudaEventDisableTiming);

    cudaEventRecord(ev_fork, 0);
    cudaStreamWaitEvent(s2, ev_fork, 0);

    gemm_wmma_kernel<<<(N_NODES + 63) / 64, 128, 0, s2>>>(x, W, b, h0);
    cudaEventRecord(ev_join, s2);

    // Main stream: CSR build
    cudaMemsetAsync(cnt, 0, N_NODES * sizeof(int), 0);
    hist_kernel<<<(N_EDGES + 255) / 256, 256>>>(ei);
    scan_kernel<<<1, 1024>>>();
    scatter_kernel<<<(N_EDGES + 255) / 256, 256>>>(ei, attr);

    cudaStreamWaitEvent(0, ev_join, 0);

    // 3 SPMM rounds: h0 -> h1 -> h0 -> d_out (fp32)
    int blocks = (N_NODES / 2 * 32 + 255) / 256;
    spmm_kernel<false><<<blocks, 256>>>(h0, h1);
    spmm_kernel<false><<<blocks, 256>>>(h1, h0);
    spmm_kernel<true ><<<blocks, 256>>>(h0, out);
}

// round 7
// speedup vs baseline: 1.7150x; 1.5888x over previous
#include <cuda_runtime.h>
#include <cuda_fp16.h>
#include <mma.h>

using namespace nvcuda;

// Problem constants
#define N_NODES 50000
#define N_EDGES 800000
#define IN_F    128
#define OUT_F   64
#define NBLK_SCAN 196            // ceil(50000/256)

// ---------------------------------------------------------------------------
// Device scratch (no allocations allowed)
// ---------------------------------------------------------------------------
__device__ int    g_row_cnt[N_NODES];          // histogram, then scatter cursor
__device__ int    g_row_ptr[N_NODES + 1];      // CSR row pointers
__device__ int    g_part[NBLK_SCAN];           // per-block partial sums
__device__ int2   g_edge_sorted[N_EDGES];      // packed (col*16, attr-bits fp32)
__device__ __half g_h0[N_NODES * OUT_F];       // ping (fp16 features)
__device__ __half g_h1[N_NODES * OUT_F];       // pong (fp16 features)

// ---------------------------------------------------------------------------
// histogram of destination rows; 1 edge/thread
// ---------------------------------------------------------------------------
__global__ void hist_kernel(const int* __restrict__ ei) {
    int e = blockIdx.x * blockDim.x + threadIdx.x;
    if (e < N_EDGES) atomicAdd(&g_row_cnt[ei[e]], 1);
}

// ---------------------------------------------------------------------------
// scan phase 1: per-block (256 counters) partial sums  [196 blocks]
// ---------------------------------------------------------------------------
__global__ void scan_partial_kernel() {
    __shared__ int sm[256];
    int t = threadIdx.x;
    int i = blockIdx.x * 256 + t;
    sm[t] = (i < N_NODES) ? g_row_cnt[i] : 0;
    __syncthreads();
#pragma unroll
    for (int off = 128; off > 0; off >>= 1) {
        if (t < off) sm[t] += sm[t + off];
        __syncthreads();
    }
    if (t == 0) g_part[blockIdx.x] = sm[0];
}

// ---------------------------------------------------------------------------
// scan phase 2: exclusive scan of the 196 partials  [1 block, tiny]
// ---------------------------------------------------------------------------
__global__ void scan_tops_kernel() {
    __shared__ int sm[256];
    int t = threadIdx.x;
    int orig = (t < NBLK_SCAN) ? g_part[t] : 0;
    sm[t] = orig;
    __syncthreads();
    int v = orig;
    for (int off = 1; off < 256; off <<= 1) {
        int add = (t >= off) ? sm[t - off] : 0;
        __syncthreads();
        v += add;
        sm[t] = v;
        __syncthreads();
    }
    if (t < NBLK_SCAN) g_part[t] = v - orig;   // exclusive
}

// ---------------------------------------------------------------------------
// scan phase 3: local exclusive scan + block offset -> row_ptr & cursor
// ---------------------------------------------------------------------------
__global__ void scan_apply_kernel() {
    __shared__ int sm[256];
    int t = threadIdx.x;
    int i = blockIdx.x * 256 + t;
    int c = (i < N_NODES) ? g_row_cnt[i] : 0;
    sm[t] = c;
    __syncthreads();
    int v = c;
    for (int off = 1; off < 256; off <<= 1) {
        int add = (t >= off) ? sm[t - off] : 0;
        __syncthreads();
        v += add;
        sm[t] = v;
        __syncthreads();
    }
    int excl = v - c + g_part[blockIdx.x];
    if (i < N_NODES) {
        g_row_ptr[i] = excl;
        g_row_cnt[i] = excl;   // scatter cursor
    }
    if (blockIdx.x == 0 && t == 0) g_row_ptr[N_NODES] = N_EDGES;
}

// ---------------------------------------------------------------------------
// scatter edges into CSR order; 1 edge/thread.
// Stores col pre-scaled by 16 (uint2 index) to save an IMAD in spmm.
// ---------------------------------------------------------------------------
__global__ void scatter_kernel(const int* __restrict__ ei,
                               const float* __restrict__ attr) {
    int e = blockIdx.x * blockDim.x + threadIdx.x;
    if (e < N_EDGES) {
        int row = ei[e];
        int col = ei[N_EDGES + e];
        float a = attr[e];
        int pos = atomicAdd(&g_row_cnt[row], 1);
        g_edge_sorted[pos] = make_int2(col * 16, __float_as_int(a));
    }
}

// ---------------------------------------------------------------------------
// GEMM via tensor cores: out[n,o] = sum_k x[n,k] * W[o,k] + b[o]
// fp16 inputs (converted on the fly), fp32 accumulate, fp16 store.
// ---------------------------------------------------------------------------
__global__ __launch_bounds__(128)
void gemm_wmma_kernel(const float* __restrict__ x,
                      const float* __restrict__ W,
                      const float* __restrict__ b,
                      __half* __restrict__ out) {
    __shared__ __half Xs[64 * 128];
    __shared__ __half Wsh[64 * 128];

    int tid  = threadIdx.x;
    int warp = tid >> 5;
    int lane = tid & 31;
    int row0 = blockIdx.x * 64;

    for (int i = tid; i < 64 * 128 / 4; i += 128) {
        float4 v = __ldg((const float4*)W + i);
        __half2 h0 = __floats2half2_rn(v.x, v.y);
        __half2 h1 = __floats2half2_rn(v.z, v.w);
        ((__half2*)Wsh)[i * 2]     = h0;
        ((__half2*)Wsh)[i * 2 + 1] = h1;
    }
    for (int i = tid; i < 64 * 128 / 4; i += 128) {
        int r = i >> 5;
        int c = i & 31;
        int gr = row0 + r;
        if (gr >= N_NODES) gr = N_NODES - 1;
        float4 v = __ldg((const float4*)&x[gr * IN_F] + c);
        __half2 h0 = __floats2half2_rn(v.x, v.y);
        __half2 h1 = __floats2half2_rn(v.z, v.w);
        ((__half2*)Xs)[i * 2]     = h0;
        ((__half2*)Xs)[i * 2 + 1] = h1;
    }
    __syncthreads();

    wmma::fragment<wmma::accumulator, 16, 16, 16, float> acc[4];
#pragma unroll
    for (int j = 0; j < 4; j++) wmma::fill_fragment(acc[j], 0.0f);

#pragma unroll
    for (int k = 0; k < IN_F; k += 16) {
        wmma::fragment<wmma::matrix_a, 16, 16, 16, __half, wmma::row_major> af;
        wmma::load_matrix_sync(af, Xs + (warp * 16) * 128 + k, 128);
#pragma unroll
        for (int j = 0; j < 4; j++) {
            wmma::fragment<wmma::matrix_b, 16, 16, 16, __half, wmma::col_major> bf;
            wmma::load_matrix_sync(bf, Wsh + (j * 16) * 128 + k, 128);
            wmma::mma_sync(acc[j], af, bf, acc[j]);
        }
    }

    __syncthreads();
    float* stage = (float*)Xs;
    float* st = stage + warp * 16 * 64;
#pragma unroll
    for (int j = 0; j < 4; j++)
        wmma::store_matrix_sync(st + j * 16, acc[j], 64, wmma::mem_row_major);
    __syncwarp();

    for (int it = lane; it < 16 * 16; it += 32) {
        int r  = it >> 4;
        int c4 = it & 15;
        int gr = row0 + warp * 16 + r;
        if (gr < N_NODES) {
            float4 bias = __ldg((const float4*)b + c4);
            float v0 = st[r * 64 + c4 * 4 + 0] + bias.x;
            float v1 = st[r * 64 + c4 * 4 + 1] + bias.y;
            float v2 = st[r * 64 + c4 * 4 + 2] + bias.z;
            float v3 = st[r * 64 + c4 * 4 + 3] + bias.w;
            __half2 h0 = __floats2half2_rn(v0, v1);
            __half2 h1 = __floats2half2_rn(v2, v3);
            uint2 u;
            u.x = *(unsigned int*)&h0;
            u.y = *(unsigned int*)&h1;
            ((uint2*)out)[gr * 16 + c4] = u;
        }
    }
}

// ---------------------------------------------------------------------------
// SPMM (CSR): 2 rows/warp, 16 lanes/row, 4 fp16 feats per lane (8B gather).
// fp32 accumulate. FINAL=true writes fp32 to d_out, else fp16.
// Edge payload carries col*16 (pre-scaled uint2 index).
// ---------------------------------------------------------------------------
template <bool FINAL>
__global__ __launch_bounds__(256, 8)
void spmm_kernel(const __half* __restrict__ in, void* __restrict__ outv) {
    int warp = (blockIdx.x * blockDim.x + threadIdx.x) >> 5;
    int lane = threadIdx.x & 31;
    int half_id = lane >> 4;
    int fl      = lane & 15;

    int row = warp * 2 + half_id;
    if (row >= N_NODES) return;

    int s = __ldg(&g_row_ptr[row]);
    int e = __ldg(&g_row_ptr[row + 1]);

    const uint2* inp = (const uint2*)in;
    float4 a0 = make_float4(0.f, 0.f, 0.f, 0.f);
    float4 a1 = make_float4(0.f, 0.f, 0.f, 0.f);
    float4 a2 = make_float4(0.f, 0.f, 0.f, 0.f);
    float4 a3 = make_float4(0.f, 0.f, 0.f, 0.f);

    int i = s;
    for (; i + 4 <= e; i += 4) {
        int2 e0 = __ldg(&g_edge_sorted[i]);
        int2 e1 = __ldg(&g_edge_sorted[i + 1]);
        int2 e2 = __ldg(&g_edge_sorted[i + 2]);
        int2 e3 = __ldg(&g_edge_sorted[i + 3]);
        uint2 v0 = __ldg(&inp[e0.x + fl]);
        uint2 v1 = __ldg(&inp[e1.x + fl]);
        uint2 v2 = __ldg(&inp[e2.x + fl]);
        uint2 v3 = __ldg(&inp[e3.x + fl]);
        float w0 = __int_as_float(e0.y);
        float w1 = __int_as_float(e1.y);
        float w2 = __int_as_float(e2.y);
        float w3 = __int_as_float(e3.y);

        float2 f;
        f = __half22float2(*(__half2*)&v0.x); a0.x += w0 * f.x; a0.y += w0 * f.y;
        f = __half22float2(*(__half2*)&v0.y); a0.z += w0 * f.x; a0.w += w0 * f.y;
        f = __half22float2(*(__half2*)&v1.x); a1.x += w1 * f.x; a1.y += w1 * f.y;
        f = __half22float2(*(__half2*)&v1.y); a1.z += w1 * f.x; a1.w += w1 * f.y;
        f = __half22float2(*(__half2*)&v2.x); a2.x += w2 * f.x; a2.y += w2 * f.y;
        f = __half22float2(*(__half2*)&v2.y); a2.z += w2 * f.x; a2.w += w2 * f.y;
        f = __half22float2(*(__half2*)&v3.x); a3.x += w3 * f.x; a3.y += w3 * f.y;
        f = __half22float2(*(__half2*)&v3.y); a3.z += w3 * f.x; a3.w += w3 * f.y;
    }
    for (; i < e; i++) {
        int2 ed = __ldg(&g_edge_sorted[i]);
        uint2 v = __ldg(&inp[ed.x + fl]);
        float w = __int_as_float(ed.y);
        float2 f;
        f = __half22float2(*(__half2*)&v.x); a0.x += w * f.x; a0.y += w * f.y;
        f = __half22float2(*(__half2*)&v.y); a0.z += w * f.x; a0.w += w * f.y;
    }

    float4 acc;
    acc.x = (a0.x + a1.x) + (a2.x + a3.x);
    acc.y = (a0.y + a1.y) + (a2.y + a3.y);
    acc.z = (a0.z + a1.z) + (a2.z + a3.z);
    acc.w = (a0.w + a1.w) + (a2.w + a3.w);

    if (FINAL) {
        ((float4*)outv)[row * 16 + fl] = acc;
    } else {
        __half2 h0 = __floats2half2_rn(acc.x, acc.y);
        __half2 h1 = __floats2half2_rn(acc.z, acc.w);
        uint2 st;
        st.x = *(unsigned int*)&h0;
        st.y = *(unsigned int*)&h1;
        ((uint2*)outv)[row * 16 + fl] = st;
    }
}

// ---------------------------------------------------------------------------
// launch: fork GEMM onto a side stream, overlapping with CSR build
// ---------------------------------------------------------------------------
extern "C" void kernel_launch(void* const* d_in, const int* in_sizes, int n_in,
                              void* d_out, int out_size) {
    const float* x    = (const float*)d_in[0];
    const int*   ei   = (const int*)d_in[1];   // int32 (JAX x64 disabled)
    const float* attr = (const float*)d_in[2];
    const float* W    = (const float*)d_in[3];
    const float* b    = (const float*)d_in[4];
    float*       out  = (float*)d_out;

    __half *h0, *h1;
    int    *cnt;
    cudaGetSymbolAddress((void**)&h0,  g_h0);
    cudaGetSymbolAddress((void**)&h1,  g_h1);
    cudaGetSymbolAddress((void**)&cnt, g_row_cnt);

    // Fork side stream for the independent GEMM.
    cudaStream_t s2;
    cudaStreamCreateWithFlags(&s2, cudaStreamNonBlocking);
    cudaEvent_t ev_fork, ev_join;
    cudaEventCreateWithFlags(&ev_fork, cudaEventDisableTiming);
    cudaEventCreateWithFlags(&ev_join, cudaEventDisableTiming);

    cudaEventRecord(ev_fork, 0);
    cudaStreamWaitEvent(s2, ev_fork, 0);

    gemm_wmma_kernel<<<(N_NODES + 63) / 64, 128, 0, s2>>>(x, W, b, h0);
    cudaEventRecord(ev_join, s2);

    // Main stream: CSR build (scan now full-chip, 3 phases)
    cudaMemsetAsync(cnt, 0, N_NODES * sizeof(int), 0);
    hist_kernel<<<(N_EDGES + 255) / 256, 256>>>(ei);
    scan_partial_kernel<<<NBLK_SCAN, 256>>>();
    scan_tops_kernel<<<1, 256>>>();
    scan_apply_kernel<<<NBLK_SCAN, 256>>>();
    scatter_kernel<<<(N_EDGES + 255) / 256, 256>>>(ei, attr);

    cudaStreamWaitEvent(0, ev_join, 0);

    // 3 SPMM rounds: h0 -> h1 -> h0 -> d_out (fp32)
    int blocks = (N_NODES / 2 * 32 + 255) / 256;
    spmm_kernel<false><<<blocks, 256>>>(h0, h1);
    spmm_kernel<false><<<blocks, 256>>>(h1, h0);
    spmm_kernel<true ><<<blocks, 256>>>(h0, out);
}